// round 13
// baseline (speedup 1.0000x reference)
#include <cuda_runtime.h>
#include <cuda_fp16.h>

// Problem constants (fixed by the reference).
#define NN 100000
#define DD 64
#define NROW4 16             // float4s per 64-float fp32 row
#define NE 1600000
#define NB 98                // ceil(NN / 1024) scan blocks
#define NE_PAD (NE + 4 * NN) // padded adjacency capacity (gaps never read)
#define READYBIT 0x40000000

// Chebyshev coefficients for lambda_max = 2.0 (constant-fold: C1A=-1, C1B=0,
// C2A=-2, C2B=0).
#define C1A (-2.0f / 2.0f)
#define C1B (2.0f / 2.0f - 1.0f)
#define C2A (-4.0f / 2.0f)
#define C2B (4.0f / 2.0f - 2.0f)

typedef unsigned long long ull;

// Scratch (device globals: no allocation allowed in kernel_launch).
__device__ int    g_degi  [NN];
__device__ int    g_rank  [NE];         // per-edge arrival rank within dst
__device__ int    g_tot   [128];        // per-block padded totals | READYBIT
__device__ int    g_rowptr[NN];         // aligned segment starts (mult. of 4)
__device__ __align__(16) int g_adj[NE_PAD];
__device__ float  g_norm  [NN];
__device__ float  g_norm2 [NN];
__device__ uint4  g_xs16  [NN * 8];     // fp16 rows: norm[s]*feat[s]
__device__ uint4  g_y16   [NN * 8];     // fp16 rows: norm2[s]*h0[s]
__device__ float4 g_h0    [NN * NROW4]; // fp32 aggregation sums, pass 1
__device__ float4 g_h1    [NN * NROW4]; // fp32 aggregation sums, pass 2 (xC1A)

// ---------------------------------------------------------------------------
// bit-cast helpers (no HW cost)
// ---------------------------------------------------------------------------
__device__ __forceinline__ float2 u32_to_f2(unsigned u) {
    __half2 h = *reinterpret_cast<__half2*>(&u);
    return __half22float2(h);
}
__device__ __forceinline__ unsigned h2_to_u32(__half2 h) {
    return *reinterpret_cast<unsigned*>(&h);
}

// ---------------------------------------------------------------------------
// f32x2 packed-FMA helpers (Blackwell)
// ---------------------------------------------------------------------------
__device__ __forceinline__ ull pack2(float v) {
    ull r;
    asm("mov.b64 %0, {%1, %1};" : "=l"(r) : "f"(v));
    return r;
}
__device__ __forceinline__ void fma2(ull& d, ull a, ull b) {
    asm("fma.rn.f32x2 %0, %1, %2, %0;" : "+l"(d) : "l"(a), "l"(b));
}
__device__ __forceinline__ float2 unpack2(ull v) {
    float2 r;
    asm("mov.b64 {%0, %1}, %2;" : "=f"(r.x), "=f"(r.y) : "l"(v));
    return r;
}

// ---------------------------------------------------------------------------
// 1) degree histogram + rank capture: rank[e] = old deg[dst[e]]++
//    The atomic return value is the edge's slot within its destination's
//    segment — recorded so fill_kernel needs NO atomics.
// ---------------------------------------------------------------------------
__global__ void deg_kernel(const int4* __restrict__ dst4) {
    int t = blockIdx.x * blockDim.x + threadIdx.x;
    if (t < NE / 4) {
        int4 d = __ldg(dst4 + t);
        int4 r;
        r.x = atomicAdd(&g_degi[d.x], 1);
        r.y = atomicAdd(&g_degi[d.y], 1);
        r.z = atomicAdd(&g_degi[d.z], 1);
        r.w = atomicAdd(&g_degi[d.w], 1);
        reinterpret_cast<int4*>(g_rank)[t] = r;
    }
}

// ---------------------------------------------------------------------------
// 2) single-kernel scan (decoupled lookback, 98 co-resident blocks):
//    exclusive scan of PADDED degrees -> aligned starts; also norm / norm2.
// ---------------------------------------------------------------------------
__global__ __launch_bounds__(1024) void scan_kernel() {
    __shared__ int wsum[32];
    __shared__ int pre[128];
    __shared__ int s_off;
    int tid = threadIdx.x, lane = tid & 31, wid = tid >> 5;
    int b = blockIdx.x;
    int i = b * 1024 + tid;
    int deg = (i < NN) ? g_degi[i] : 0;
    int v = (deg + 3) & ~3;          // padded degree (aligned segment size)
    int x = v;
#pragma unroll
    for (int off = 1; off < 32; off <<= 1) {
        int y = __shfl_up_sync(~0u, x, off);
        if (lane >= off) x += y;
    }
    if (lane == 31) wsum[wid] = x;
    __syncthreads();
    if (wid == 0) {
        int w = wsum[lane];
#pragma unroll
        for (int off = 1; off < 32; off <<= 1) {
            int y = __shfl_up_sync(~0u, w, off);
            if (lane >= off) w += y;
        }
        wsum[lane] = w;
    }
    __syncthreads();
    int warpoff = (wid > 0) ? wsum[wid - 1] : 0;
    int btotal  = wsum[31];

    if (tid == 0) atomicExch(&g_tot[b], btotal | READYBIT);

    if (tid < b) {
        int p;
        do { p = atomicAdd(&g_tot[tid], 0); } while (!(p & READYBIT));
        pre[tid] = p & ~READYBIT;
    } else if (tid < 128) {
        pre[tid] = 0;
    }
    __syncthreads();
    if (wid == 0) {
        int s = pre[lane] + pre[lane + 32] + pre[lane + 64] + pre[lane + 96];
#pragma unroll
        for (int off = 16; off > 0; off >>= 1)
            s += __shfl_down_sync(~0u, s, off);
        if (lane == 0) s_off = s;
    }
    __syncthreads();

    if (i < NN) {
        int ex = s_off + warpoff + x - v;   // exclusive padded prefix
        g_rowptr[i] = ex;
        float nv = rsqrtf(fmaxf((float)deg, 1.0f));
        g_norm[i]  = nv;
        g_norm2[i] = nv * nv;
    }
}

// ---------------------------------------------------------------------------
// 3) CSR fill (ATOMIC-FREE): adj[rowptr[dst] + rank[e]] = src
// ---------------------------------------------------------------------------
__global__ void fill_kernel(const int4* __restrict__ src4,
                            const int4* __restrict__ dst4) {
    int t = blockIdx.x * blockDim.x + threadIdx.x;
    if (t < NE / 4) {
        int4 s = __ldg(src4 + t);
        int4 d = __ldg(dst4 + t);
        int4 r = reinterpret_cast<const int4*>(g_rank)[t];
        g_adj[__ldg(&g_rowptr[d.x]) + r.x] = s.x;
        g_adj[__ldg(&g_rowptr[d.y]) + r.y] = s.y;
        g_adj[__ldg(&g_rowptr[d.z]) + r.z] = s.z;
        g_adj[__ldg(&g_rowptr[d.w]) + r.w] = s.w;
    }
}

// ---------------------------------------------------------------------------
// 4) scale16: xs16[i] = half(norm[i] * feat[i])   (8 threads per row)
// ---------------------------------------------------------------------------
__global__ void scale16_kernel(const float4* __restrict__ feat4) {
    int t = blockIdx.x * blockDim.x + threadIdx.x;   // grid covers NN*8 exactly
    int i = t >> 3;
    int c = t & 7;
    float nv = g_norm[i];
    float4 f0 = __ldg(feat4 + (i << 4) + c * 2);
    float4 f1 = __ldg(feat4 + (i << 4) + c * 2 + 1);
    uint4 u;
    u.x = h2_to_u32(__floats2half2_rn(nv * f0.x, nv * f0.y));
    u.y = h2_to_u32(__floats2half2_rn(nv * f0.z, nv * f0.w));
    u.z = h2_to_u32(__floats2half2_rn(nv * f1.x, nv * f1.y));
    u.w = h2_to_u32(__floats2half2_rn(nv * f1.z, nv * f1.w));
    g_xs16[t] = u;
}

// ---------------------------------------------------------------------------
// 5) gather passes. 8 threads per node; each thread owns 8 halves (16B).
//    One LDG.128 per edge per thread; fp32 accumulation; no scalar loads.
//    PASS 0: h0[i] = sum xs16[s]; epilogue writes h0 (fp32) and
//            y16[i] = half(norm2[i]*h0[i]).
//    PASS 1: h1[i] = C1A * sum y16[s]  (fp32).
// ---------------------------------------------------------------------------
template <int PASS>
__global__ __launch_bounds__(256) void gather_kernel() {
    int t = blockIdx.x * blockDim.x + threadIdx.x;   // grid covers NN*8 exactly
    int i = t >> 3;
    int c = t & 7;

    int j   = g_rowptr[i];       // multiple of 4
    int end = j + g_degi[i];
    const uint4* __restrict__ src = (PASS == 0) ? g_xs16 : g_y16;

    float a0 = 0.f, a1 = 0.f, a2 = 0.f, a3 = 0.f;
    float a4 = 0.f, a5 = 0.f, a6 = 0.f, a7 = 0.f;
    float b0 = 0.f, b1 = 0.f, b2 = 0.f, b3 = 0.f;
    float b4 = 0.f, b5 = 0.f, b6 = 0.f, b7 = 0.f;

#define EDGE_ACC(P0,P1,P2,P3,P4,P5,P6,P7, S)                                 \
    {                                                                        \
        uint4 u = __ldg(src + ((S) << 3) + c);                               \
        float2 f0 = u32_to_f2(u.x);                                          \
        float2 f1 = u32_to_f2(u.y);                                          \
        float2 f2 = u32_to_f2(u.z);                                          \
        float2 f3 = u32_to_f2(u.w);                                          \
        P0 += f0.x; P1 += f0.y; P2 += f1.x; P3 += f1.y;                      \
        P4 += f2.x; P5 += f2.y; P6 += f3.x; P7 += f3.y;                      \
    }
#define EDGE_A(S) EDGE_ACC(a0,a1,a2,a3,a4,a5,a6,a7, S)
#define EDGE_B(S) EDGE_ACC(b0,b1,b2,b3,b4,b5,b6,b7, S)

    for (; j + 8 <= end; j += 8) {
        int4 p0 = *reinterpret_cast<const int4*>(&g_adj[j]);
        int4 p1 = *reinterpret_cast<const int4*>(&g_adj[j + 4]);
        EDGE_A(p0.x); EDGE_B(p0.y); EDGE_A(p0.z); EDGE_B(p0.w);
        EDGE_A(p1.x); EDGE_B(p1.y); EDGE_A(p1.z); EDGE_B(p1.w);
    }
    if (j + 4 <= end) {
        int4 p0 = *reinterpret_cast<const int4*>(&g_adj[j]);
        EDGE_A(p0.x); EDGE_B(p0.y); EDGE_A(p0.z); EDGE_B(p0.w);
        j += 4;
    }
    for (; j < end; j++) {
        EDGE_A(g_adj[j]);
    }
#undef EDGE_A
#undef EDGE_B
#undef EDGE_ACC

    float r0 = a0 + b0, r1 = a1 + b1, r2 = a2 + b2, r3 = a3 + b3;
    float r4 = a4 + b4, r5 = a5 + b5, r6 = a6 + b6, r7 = a7 + b7;

    if (PASS == 0) {
        g_h0[(i << 4) + c * 2]     = make_float4(r0, r1, r2, r3);
        g_h0[(i << 4) + c * 2 + 1] = make_float4(r4, r5, r6, r7);
        float n2 = g_norm2[i];
        uint4 u;
        u.x = h2_to_u32(__floats2half2_rn(n2 * r0, n2 * r1));
        u.y = h2_to_u32(__floats2half2_rn(n2 * r2, n2 * r3));
        u.z = h2_to_u32(__floats2half2_rn(n2 * r4, n2 * r5));
        u.w = h2_to_u32(__floats2half2_rn(n2 * r6, n2 * r7));
        g_y16[t] = u;
    } else {
        g_h1[(i << 4) + c * 2] =
            make_float4(C1A * r0, C1A * r1, C1A * r2, C1A * r3);
        g_h1[(i << 4) + c * 2 + 1] =
            make_float4(C1A * r4, C1A * r5, C1A * r6, C1A * r7);
    }
}

// ---------------------------------------------------------------------------
// 6) fused epilogue GEMM (proven):
//    t0 = feat;  t1 = c1a*n*h0;  t2 = c2a*n*h1 + c2b*t1 - t0
//    out = t0@W0 + t1@W1 + t2@W2 + bias
// ---------------------------------------------------------------------------
__global__ __launch_bounds__(256) void final_kernel(
    const float4* __restrict__ feat4,
    const float4* __restrict__ W4,
    const float4* __restrict__ bias4,
    float4* __restrict__ out4) {
    __shared__ __align__(16) float Ws[3 * 64 * 64];   // 49152 B
    {
        float4* Ws4 = reinterpret_cast<float4*>(Ws);
        for (int i = threadIdx.x; i < 3 * 64 * 16; i += 256)
            Ws4[i] = __ldg(W4 + i);
    }
    __syncthreads();

    const int cg   = threadIdx.x >> 6;
    const int rg   = threadIdx.x & 63;
    const int base = blockIdx.x * 256;

    int   rows[4];
    bool  valid[4];
    float n[4];
#pragma unroll
    for (int r = 0; r < 4; r++) {
        int row  = base + rg + 64 * r;
        valid[r] = row < NN;
        rows[r]  = valid[r] ? row : 0;
        n[r]     = g_norm[rows[r]];
    }

    ull acc[4][8];
#pragma unroll
    for (int r = 0; r < 4; r++)
#pragma unroll
        for (int cp = 0; cp < 8; cp++) acc[r][cp] = 0ULL;

    const ulonglong2* Wp = reinterpret_cast<const ulonglong2*>(Ws);

    for (int dc = 0; dc < 16; dc++) {
        float4 a0[4], a1[4], a2[4];
#pragma unroll
        for (int r = 0; r < 4; r++) {
            int b = (rows[r] << 4) + dc;
            a0[r] = __ldg(feat4 + b);
            a1[r] = g_h0[b];
            a2[r] = g_h1[b];
        }
#pragma unroll
        for (int s = 0; s < 4; s++) {
            const int d = dc * 4 + s;
            ull tt[3][4];
#pragma unroll
            for (int r = 0; r < 4; r++) {
                float t0  = reinterpret_cast<const float*>(&a0[r])[s];
                float h0v = reinterpret_cast<const float*>(&a1[r])[s];
                float h1v = reinterpret_cast<const float*>(&a2[r])[s];
                float t1 = fmaf(C1A * n[r], h0v, C1B * t0);
                float t2 = fmaf(C2A * n[r], h1v, fmaf(C2B, t1, -t0));
                tt[0][r] = pack2(t0);
                tt[1][r] = pack2(t1);
                tt[2][r] = pack2(t2);
            }
#pragma unroll
            for (int k = 0; k < 3; k++) {
                const ulonglong2* p = Wp + (k * 1024 + d * 16 + cg * 4);
                ull w[8];
#pragma unroll
                for (int j = 0; j < 4; j++) {
                    ulonglong2 v = p[j];       // LDS.128, warp-uniform broadcast
                    w[2 * j]     = v.x;
                    w[2 * j + 1] = v.y;
                }
#pragma unroll
                for (int r = 0; r < 4; r++)
#pragma unroll
                    for (int cp = 0; cp < 8; cp++)
                        fma2(acc[r][cp], tt[k][r], w[cp]);
            }
        }
    }

    float4 b4[4];
#pragma unroll
    for (int j = 0; j < 4; j++) b4[j] = __ldg(bias4 + cg * 4 + j);
#pragma unroll
    for (int r = 0; r < 4; r++) {
        if (!valid[r]) continue;
#pragma unroll
        for (int j = 0; j < 4; j++) {
            float2 lo = unpack2(acc[r][2 * j]);
            float2 hi = unpack2(acc[r][2 * j + 1]);
            float4 o;
            o.x = lo.x + b4[j].x;
            o.y = lo.y + b4[j].y;
            o.z = hi.x + b4[j].z;
            o.w = hi.y + b4[j].w;
            out4[(rows[r] << 4) + cg * 4 + j] = o;
        }
    }
}

// ---------------------------------------------------------------------------
// launch (graph-capturable: only async memsets + kernel launches, one stream)
// ---------------------------------------------------------------------------
extern "C" void kernel_launch(void* const* d_in, const int* in_sizes, int n_in,
                              void* d_out, int out_size) {
    const float* feat = (const float*)d_in[0];
    const float* W    = (const float*)d_in[1];
    const float* bias = (const float*)d_in[2];
    const int*   esrc = (const int*)d_in[3];
    const int*   edst = (const int*)d_in[4];
    float*       out  = (float*)d_out;

    void *p_degi = nullptr, *p_tot = nullptr;
    cudaGetSymbolAddress(&p_degi, g_degi);
    cudaGetSymbolAddress(&p_tot,  g_tot);
    cudaMemsetAsync(p_degi, 0, NN * sizeof(int));
    cudaMemsetAsync(p_tot,  0, 128 * sizeof(int));

    const int T = 256;

    deg_kernel<<<(NE / 4 + T - 1) / T, T>>>((const int4*)edst);
    scan_kernel<<<NB, 1024>>>();
    fill_kernel<<<(NE / 4 + T - 1) / T, T>>>((const int4*)esrc, (const int4*)edst);
    scale16_kernel<<<NN * 8 / T, T>>>((const float4*)feat);

    gather_kernel<0><<<NN * 8 / T, T>>>();
    gather_kernel<1><<<NN * 8 / T, T>>>();

    final_kernel<<<(NN + 255) / 256, 256>>>((const float4*)feat,
                                            (const float4*)W,
                                            (const float4*)bias,
                                            (float4*)out);
}

// round 14
// speedup vs baseline: 1.0005x; 1.0005x over previous
#include <cuda_runtime.h>
#include <cuda_fp16.h>

// Problem constants (fixed by the reference).
#define NN 100000
#define DD 64
#define NROW4 16             // float4s per 64-float fp32 row
#define NE 1600000
#define NB 98                // ceil(NN / 1024) scan blocks
#define NE_PAD (NE + 4 * NN) // padded adjacency capacity (gaps never read)
#define READYBIT 0x40000000

// Fused fill+scale grid split: fill = 8 edges/thread.
#define FILL_B ((NE / 8 + 255) / 256)   // 782 blocks
#define SCALE_B (NN * 8 / 256)          // 3125 blocks

// Chebyshev coefficients for lambda_max = 2.0 (constant-fold: C1A=-1, C1B=0,
// C2A=-2, C2B=0).
#define C1A (-2.0f / 2.0f)
#define C1B (2.0f / 2.0f - 1.0f)
#define C2A (-4.0f / 2.0f)
#define C2B (4.0f / 2.0f - 2.0f)

typedef unsigned long long ull;

// Scratch (device globals: no allocation allowed in kernel_launch).
__device__ int    g_degi  [NN];
__device__ int    g_tot   [128];        // per-block padded totals | READYBIT
__device__ int    g_rowptr[NN];         // aligned segment starts (mult. of 4)
__device__ int    g_cursor[NN];
__device__ __align__(16) int g_adj[NE_PAD];
__device__ float  g_norm  [NN];
__device__ float  g_norm2 [NN];
__device__ uint4  g_xs16  [NN * 8];     // fp16 rows: norm[s]*feat[s]
__device__ uint4  g_y16   [NN * 8];     // fp16 rows: norm2[s]*h0[s]
__device__ float4 g_h0    [NN * NROW4]; // fp32 aggregation sums, pass 1
__device__ float4 g_h1    [NN * NROW4]; // fp32 aggregation sums, pass 2 (xC1A)

// ---------------------------------------------------------------------------
// bit-cast helpers (no HW cost)
// ---------------------------------------------------------------------------
__device__ __forceinline__ float2 u32_to_f2(unsigned u) {
    __half2 h = *reinterpret_cast<__half2*>(&u);
    return __half22float2(h);
}
__device__ __forceinline__ unsigned h2_to_u32(__half2 h) {
    return *reinterpret_cast<unsigned*>(&h);
}

// ---------------------------------------------------------------------------
// f32x2 packed-FMA helpers (Blackwell)
// ---------------------------------------------------------------------------
__device__ __forceinline__ ull pack2(float v) {
    ull r;
    asm("mov.b64 %0, {%1, %1};" : "=l"(r) : "f"(v));
    return r;
}
__device__ __forceinline__ void fma2(ull& d, ull a, ull b) {
    asm("fma.rn.f32x2 %0, %1, %2, %0;" : "+l"(d) : "l"(a), "l"(b));
}
__device__ __forceinline__ float2 unpack2(ull v) {
    float2 r;
    asm("mov.b64 {%0, %1}, %2;" : "=f"(r.x), "=f"(r.y) : "l"(v));
    return r;
}

// ---------------------------------------------------------------------------
// 1) degree histogram: deg[dst] += 1 (return discarded -> REDG, fast path)
// ---------------------------------------------------------------------------
__global__ void deg_kernel(const int4* __restrict__ dst4) {
    int t = blockIdx.x * blockDim.x + threadIdx.x;
    if (t < NE / 4) {
        int4 d = __ldg(dst4 + t);
        atomicAdd(&g_degi[d.x], 1);
        atomicAdd(&g_degi[d.y], 1);
        atomicAdd(&g_degi[d.z], 1);
        atomicAdd(&g_degi[d.w], 1);
    }
}

// ---------------------------------------------------------------------------
// 2) single-kernel scan (decoupled lookback, 98 co-resident blocks):
//    exclusive scan of PADDED degrees -> aligned starts; also norm / norm2.
// ---------------------------------------------------------------------------
__global__ __launch_bounds__(1024) void scan_kernel() {
    __shared__ int wsum[32];
    __shared__ int pre[128];
    __shared__ int s_off;
    int tid = threadIdx.x, lane = tid & 31, wid = tid >> 5;
    int b = blockIdx.x;
    int i = b * 1024 + tid;
    int deg = (i < NN) ? g_degi[i] : 0;
    int v = (deg + 3) & ~3;          // padded degree (aligned segment size)
    int x = v;
#pragma unroll
    for (int off = 1; off < 32; off <<= 1) {
        int y = __shfl_up_sync(~0u, x, off);
        if (lane >= off) x += y;
    }
    if (lane == 31) wsum[wid] = x;
    __syncthreads();
    if (wid == 0) {
        int w = wsum[lane];
#pragma unroll
        for (int off = 1; off < 32; off <<= 1) {
            int y = __shfl_up_sync(~0u, w, off);
            if (lane >= off) w += y;
        }
        wsum[lane] = w;
    }
    __syncthreads();
    int warpoff = (wid > 0) ? wsum[wid - 1] : 0;
    int btotal  = wsum[31];

    if (tid == 0) atomicExch(&g_tot[b], btotal | READYBIT);

    if (tid < b) {
        int p;
        do { p = atomicAdd(&g_tot[tid], 0); } while (!(p & READYBIT));
        pre[tid] = p & ~READYBIT;
    } else if (tid < 128) {
        pre[tid] = 0;
    }
    __syncthreads();
    if (wid == 0) {
        int s = pre[lane] + pre[lane + 32] + pre[lane + 64] + pre[lane + 96];
#pragma unroll
        for (int off = 16; off > 0; off >>= 1)
            s += __shfl_down_sync(~0u, s, off);
        if (lane == 0) s_off = s;
    }
    __syncthreads();

    if (i < NN) {
        int ex = s_off + warpoff + x - v;   // exclusive padded prefix
        g_rowptr[i] = ex;
        g_cursor[i] = ex;
        float nv = rsqrtf(fmaxf((float)deg, 1.0f));
        g_norm[i]  = nv;
        g_norm2[i] = nv * nv;
    }
}

// ---------------------------------------------------------------------------
// 3) fused heterogeneous kernel:
//    blocks [0, FILL_B):        CSR fill, 8 edges/thread (8 atomics in flight)
//    blocks [FILL_B, +SCALE_B): xs16 = half(norm*feat) streaming
//    Both depend only on scan; fill's idle issue slots absorb scale work.
// ---------------------------------------------------------------------------
__global__ __launch_bounds__(256) void fill_scale_kernel(
    const int4* __restrict__ src4,
    const int4* __restrict__ dst4,
    const float4* __restrict__ feat4) {
    int b = blockIdx.x;
    if (b < FILL_B) {
        int t = b * 256 + threadIdx.x;       // 8 edges per thread
        if (t < NE / 8) {
            int h = t * 2;
            int4 s0 = __ldg(src4 + h), s1 = __ldg(src4 + h + 1);
            int4 d0 = __ldg(dst4 + h), d1 = __ldg(dst4 + h + 1);
            // 8 independent returned atomics in flight, then 8 stores.
            int c0 = atomicAdd(&g_cursor[d0.x], 1);
            int c1 = atomicAdd(&g_cursor[d0.y], 1);
            int c2 = atomicAdd(&g_cursor[d0.z], 1);
            int c3 = atomicAdd(&g_cursor[d0.w], 1);
            int c4 = atomicAdd(&g_cursor[d1.x], 1);
            int c5 = atomicAdd(&g_cursor[d1.y], 1);
            int c6 = atomicAdd(&g_cursor[d1.z], 1);
            int c7 = atomicAdd(&g_cursor[d1.w], 1);
            g_adj[c0] = s0.x; g_adj[c1] = s0.y;
            g_adj[c2] = s0.z; g_adj[c3] = s0.w;
            g_adj[c4] = s1.x; g_adj[c5] = s1.y;
            g_adj[c6] = s1.z; g_adj[c7] = s1.w;
        }
    } else {
        int t = (b - FILL_B) * 256 + threadIdx.x;   // covers NN*8 exactly
        int i = t >> 3;
        int c = t & 7;
        float nv = g_norm[i];
        float4 f0 = __ldg(feat4 + (i << 4) + c * 2);
        float4 f1 = __ldg(feat4 + (i << 4) + c * 2 + 1);
        uint4 u;
        u.x = h2_to_u32(__floats2half2_rn(nv * f0.x, nv * f0.y));
        u.y = h2_to_u32(__floats2half2_rn(nv * f0.z, nv * f0.w));
        u.z = h2_to_u32(__floats2half2_rn(nv * f1.x, nv * f1.y));
        u.w = h2_to_u32(__floats2half2_rn(nv * f1.z, nv * f1.w));
        g_xs16[t] = u;
    }
}

// ---------------------------------------------------------------------------
// 4) gather passes. 8 threads per node; each thread owns 8 halves (16B).
//    One LDG.128 per edge per thread; fp32 accumulation; no scalar loads.
//    PASS 0: h0[i] = sum xs16[s]; epilogue writes h0 (fp32) and
//            y16[i] = half(norm2[i]*h0[i]).
//    PASS 1: h1[i] = C1A * sum y16[s]  (fp32).
// ---------------------------------------------------------------------------
template <int PASS>
__global__ __launch_bounds__(256) void gather_kernel() {
    int t = blockIdx.x * blockDim.x + threadIdx.x;   // grid covers NN*8 exactly
    int i = t >> 3;
    int c = t & 7;

    int j   = g_rowptr[i];       // multiple of 4
    int end = j + g_degi[i];
    const uint4* __restrict__ src = (PASS == 0) ? g_xs16 : g_y16;

    float a0 = 0.f, a1 = 0.f, a2 = 0.f, a3 = 0.f;
    float a4 = 0.f, a5 = 0.f, a6 = 0.f, a7 = 0.f;
    float b0 = 0.f, b1 = 0.f, b2 = 0.f, b3 = 0.f;
    float b4 = 0.f, b5 = 0.f, b6 = 0.f, b7 = 0.f;

#define EDGE_ACC(P0,P1,P2,P3,P4,P5,P6,P7, S)                                 \
    {                                                                        \
        uint4 u = __ldg(src + ((S) << 3) + c);                               \
        float2 f0 = u32_to_f2(u.x);                                          \
        float2 f1 = u32_to_f2(u.y);                                          \
        float2 f2 = u32_to_f2(u.z);                                          \
        float2 f3 = u32_to_f2(u.w);                                          \
        P0 += f0.x; P1 += f0.y; P2 += f1.x; P3 += f1.y;                      \
        P4 += f2.x; P5 += f2.y; P6 += f3.x; P7 += f3.y;                      \
    }
#define EDGE_A(S) EDGE_ACC(a0,a1,a2,a3,a4,a5,a6,a7, S)
#define EDGE_B(S) EDGE_ACC(b0,b1,b2,b3,b4,b5,b6,b7, S)

    for (; j + 8 <= end; j += 8) {
        int4 p0 = *reinterpret_cast<const int4*>(&g_adj[j]);
        int4 p1 = *reinterpret_cast<const int4*>(&g_adj[j + 4]);
        EDGE_A(p0.x); EDGE_B(p0.y); EDGE_A(p0.z); EDGE_B(p0.w);
        EDGE_A(p1.x); EDGE_B(p1.y); EDGE_A(p1.z); EDGE_B(p1.w);
    }
    if (j + 4 <= end) {
        int4 p0 = *reinterpret_cast<const int4*>(&g_adj[j]);
        EDGE_A(p0.x); EDGE_B(p0.y); EDGE_A(p0.z); EDGE_B(p0.w);
        j += 4;
    }
    for (; j < end; j++) {
        EDGE_A(g_adj[j]);
    }
#undef EDGE_A
#undef EDGE_B
#undef EDGE_ACC

    float r0 = a0 + b0, r1 = a1 + b1, r2 = a2 + b2, r3 = a3 + b3;
    float r4 = a4 + b4, r5 = a5 + b5, r6 = a6 + b6, r7 = a7 + b7;

    if (PASS == 0) {
        g_h0[(i << 4) + c * 2]     = make_float4(r0, r1, r2, r3);
        g_h0[(i << 4) + c * 2 + 1] = make_float4(r4, r5, r6, r7);
        float n2 = g_norm2[i];
        uint4 u;
        u.x = h2_to_u32(__floats2half2_rn(n2 * r0, n2 * r1));
        u.y = h2_to_u32(__floats2half2_rn(n2 * r2, n2 * r3));
        u.z = h2_to_u32(__floats2half2_rn(n2 * r4, n2 * r5));
        u.w = h2_to_u32(__floats2half2_rn(n2 * r6, n2 * r7));
        g_y16[t] = u;
    } else {
        g_h1[(i << 4) + c * 2] =
            make_float4(C1A * r0, C1A * r1, C1A * r2, C1A * r3);
        g_h1[(i << 4) + c * 2 + 1] =
            make_float4(C1A * r4, C1A * r5, C1A * r6, C1A * r7);
    }
}

// ---------------------------------------------------------------------------
// 5) fused epilogue GEMM (proven):
//    t0 = feat;  t1 = c1a*n*h0;  t2 = c2a*n*h1 + c2b*t1 - t0
//    out = t0@W0 + t1@W1 + t2@W2 + bias
// ---------------------------------------------------------------------------
__global__ __launch_bounds__(256) void final_kernel(
    const float4* __restrict__ feat4,
    const float4* __restrict__ W4,
    const float4* __restrict__ bias4,
    float4* __restrict__ out4) {
    __shared__ __align__(16) float Ws[3 * 64 * 64];   // 49152 B
    {
        float4* Ws4 = reinterpret_cast<float4*>(Ws);
        for (int i = threadIdx.x; i < 3 * 64 * 16; i += 256)
            Ws4[i] = __ldg(W4 + i);
    }
    __syncthreads();

    const int cg   = threadIdx.x >> 6;
    const int rg   = threadIdx.x & 63;
    const int base = blockIdx.x * 256;

    int   rows[4];
    bool  valid[4];
    float n[4];
#pragma unroll
    for (int r = 0; r < 4; r++) {
        int row  = base + rg + 64 * r;
        valid[r] = row < NN;
        rows[r]  = valid[r] ? row : 0;
        n[r]     = g_norm[rows[r]];
    }

    ull acc[4][8];
#pragma unroll
    for (int r = 0; r < 4; r++)
#pragma unroll
        for (int cp = 0; cp < 8; cp++) acc[r][cp] = 0ULL;

    const ulonglong2* Wp = reinterpret_cast<const ulonglong2*>(Ws);

    for (int dc = 0; dc < 16; dc++) {
        float4 a0[4], a1[4], a2[4];
#pragma unroll
        for (int r = 0; r < 4; r++) {
            int b = (rows[r] << 4) + dc;
            a0[r] = __ldg(feat4 + b);
            a1[r] = g_h0[b];
            a2[r] = g_h1[b];
        }
#pragma unroll
        for (int s = 0; s < 4; s++) {
            const int d = dc * 4 + s;
            ull tt[3][4];
#pragma unroll
            for (int r = 0; r < 4; r++) {
                float t0  = reinterpret_cast<const float*>(&a0[r])[s];
                float h0v = reinterpret_cast<const float*>(&a1[r])[s];
                float h1v = reinterpret_cast<const float*>(&a2[r])[s];
                float t1 = fmaf(C1A * n[r], h0v, C1B * t0);
                float t2 = fmaf(C2A * n[r], h1v, fmaf(C2B, t1, -t0));
                tt[0][r] = pack2(t0);
                tt[1][r] = pack2(t1);
                tt[2][r] = pack2(t2);
            }
#pragma unroll
            for (int k = 0; k < 3; k++) {
                const ulonglong2* p = Wp + (k * 1024 + d * 16 + cg * 4);
                ull w[8];
#pragma unroll
                for (int j = 0; j < 4; j++) {
                    ulonglong2 v = p[j];       // LDS.128, warp-uniform broadcast
                    w[2 * j]     = v.x;
                    w[2 * j + 1] = v.y;
                }
#pragma unroll
                for (int r = 0; r < 4; r++)
#pragma unroll
                    for (int cp = 0; cp < 8; cp++)
                        fma2(acc[r][cp], tt[k][r], w[cp]);
            }
        }
    }

    float4 b4[4];
#pragma unroll
    for (int j = 0; j < 4; j++) b4[j] = __ldg(bias4 + cg * 4 + j);
#pragma unroll
    for (int r = 0; r < 4; r++) {
        if (!valid[r]) continue;
#pragma unroll
        for (int j = 0; j < 4; j++) {
            float2 lo = unpack2(acc[r][2 * j]);
            float2 hi = unpack2(acc[r][2 * j + 1]);
            float4 o;
            o.x = lo.x + b4[j].x;
            o.y = lo.y + b4[j].y;
            o.z = hi.x + b4[j].z;
            o.w = hi.y + b4[j].w;
            out4[(rows[r] << 4) + cg * 4 + j] = o;
        }
    }
}

// ---------------------------------------------------------------------------
// launch (graph-capturable: only async memsets + kernel launches, one stream)
// ---------------------------------------------------------------------------
extern "C" void kernel_launch(void* const* d_in, const int* in_sizes, int n_in,
                              void* d_out, int out_size) {
    const float* feat = (const float*)d_in[0];
    const float* W    = (const float*)d_in[1];
    const float* bias = (const float*)d_in[2];
    const int*   esrc = (const int*)d_in[3];
    const int*   edst = (const int*)d_in[4];
    float*       out  = (float*)d_out;

    void *p_degi = nullptr, *p_tot = nullptr;
    cudaGetSymbolAddress(&p_degi, g_degi);
    cudaGetSymbolAddress(&p_tot,  g_tot);
    cudaMemsetAsync(p_degi, 0, NN * sizeof(int));
    cudaMemsetAsync(p_tot,  0, 128 * sizeof(int));

    const int T = 256;

    deg_kernel<<<(NE / 4 + T - 1) / T, T>>>((const int4*)edst);
    scan_kernel<<<NB, 1024>>>();
    fill_scale_kernel<<<FILL_B + SCALE_B, T>>>((const int4*)esrc,
                                               (const int4*)edst,
                                               (const float4*)feat);

    gather_kernel<0><<<NN * 8 / T, T>>>();
    gather_kernel<1><<<NN * 8 / T, T>>>();

    final_kernel<<<(NN + 255) / 256, 256>>>((const float4*)feat,
                                            (const float4*)W,
                                            (const float4*)bias,
                                            (float4*)out);
}

// round 16
// speedup vs baseline: 1.0460x; 1.0455x over previous
#include <cuda_runtime.h>
#include <cuda_fp16.h>

// Problem constants (fixed by the reference).
#define NN 100000
#define DD 64
#define NROW4 16             // float4s per 64-float fp32 row
#define NE 1600000
#define NB 98                // ceil(NN / 1024) scan blocks
#define NE_PAD (NE + 4 * NN) // padded adjacency capacity (gaps never read)
#define READYBIT 0x40000000

// Fused fill+scale grid split: fill = 8 edges/thread.
#define FILL_B ((NE / 8 + 255) / 256)   // 782 blocks
#define SCALE_B (NN * 8 / 256)          // 3125 blocks

// Chebyshev coefficients for lambda_max = 2.0 (constant-fold: C1A=-1, C1B=0,
// C2A=-2, C2B=0).
#define C1A (-2.0f / 2.0f)
#define C1B (2.0f / 2.0f - 1.0f)
#define C2A (-4.0f / 2.0f)
#define C2B (4.0f / 2.0f - 2.0f)

typedef unsigned long long ull;

// Scratch (device globals: no allocation allowed in kernel_launch).
__device__ int    g_degi  [NN];
__device__ int    g_tot   [128];        // per-block padded totals | READYBIT
__device__ int    g_rowptr[NN];         // aligned segment starts (mult. of 4)
__device__ int    g_cursor[NN];
__device__ __align__(16) int g_adj[NE_PAD];
__device__ float  g_norm  [NN];
__device__ float  g_norm2 [NN];
__device__ uint4  g_xs16  [NN * 8];     // fp16 rows: norm[s]*feat[s]
__device__ uint4  g_y16   [NN * 8];     // fp16 rows: norm2[s]*h0[s]
__device__ float4 g_h0    [NN * NROW4]; // fp32 aggregation sums, pass 1
__device__ float4 g_h1    [NN * NROW4]; // fp32 aggregation sums, pass 2 (xC1A)

// ---------------------------------------------------------------------------
// bit-cast helpers (no HW cost)
// ---------------------------------------------------------------------------
__device__ __forceinline__ __half2 u32_to_h2(unsigned u) {
    return *reinterpret_cast<__half2*>(&u);
}
__device__ __forceinline__ float2 u32_to_f2(unsigned u) {
    return __half22float2(u32_to_h2(u));
}
__device__ __forceinline__ unsigned h2_to_u32(__half2 h) {
    return *reinterpret_cast<unsigned*>(&h);
}

// ---------------------------------------------------------------------------
// f32x2 packed-FMA helpers (Blackwell)
// ---------------------------------------------------------------------------
__device__ __forceinline__ ull pack2(float v) {
    ull r;
    asm("mov.b64 %0, {%1, %1};" : "=l"(r) : "f"(v));
    return r;
}
__device__ __forceinline__ void fma2(ull& d, ull a, ull b) {
    asm("fma.rn.f32x2 %0, %1, %2, %0;" : "+l"(d) : "l"(a), "l"(b));
}
__device__ __forceinline__ float2 unpack2(ull v) {
    float2 r;
    asm("mov.b64 {%0, %1}, %2;" : "=f"(r.x), "=f"(r.y) : "l"(v));
    return r;
}

// ---------------------------------------------------------------------------
// 1) degree histogram: deg[dst] += 1 (return discarded -> REDG, fast path)
// ---------------------------------------------------------------------------
__global__ void deg_kernel(const int4* __restrict__ dst4) {
    int t = blockIdx.x * blockDim.x + threadIdx.x;
    if (t < NE / 4) {
        int4 d = __ldg(dst4 + t);
        atomicAdd(&g_degi[d.x], 1);
        atomicAdd(&g_degi[d.y], 1);
        atomicAdd(&g_degi[d.z], 1);
        atomicAdd(&g_degi[d.w], 1);
    }
}

// ---------------------------------------------------------------------------
// 2) single-kernel scan (decoupled lookback, 98 co-resident blocks):
//    exclusive scan of PADDED degrees -> aligned starts; also norm / norm2.
// ---------------------------------------------------------------------------
__global__ __launch_bounds__(1024) void scan_kernel() {
    __shared__ int wsum[32];
    __shared__ int pre[128];
    __shared__ int s_off;
    int tid = threadIdx.x, lane = tid & 31, wid = tid >> 5;
    int b = blockIdx.x;
    int i = b * 1024 + tid;
    int deg = (i < NN) ? g_degi[i] : 0;
    int v = (deg + 3) & ~3;          // padded degree (aligned segment size)
    int x = v;
#pragma unroll
    for (int off = 1; off < 32; off <<= 1) {
        int y = __shfl_up_sync(~0u, x, off);
        if (lane >= off) x += y;
    }
    if (lane == 31) wsum[wid] = x;
    __syncthreads();
    if (wid == 0) {
        int w = wsum[lane];
#pragma unroll
        for (int off = 1; off < 32; off <<= 1) {
            int y = __shfl_up_sync(~0u, w, off);
            if (lane >= off) w += y;
        }
        wsum[lane] = w;
    }
    __syncthreads();
    int warpoff = (wid > 0) ? wsum[wid - 1] : 0;
    int btotal  = wsum[31];

    if (tid == 0) atomicExch(&g_tot[b], btotal | READYBIT);

    if (tid < b) {
        int p;
        do { p = atomicAdd(&g_tot[tid], 0); } while (!(p & READYBIT));
        pre[tid] = p & ~READYBIT;
    } else if (tid < 128) {
        pre[tid] = 0;
    }
    __syncthreads();
    if (wid == 0) {
        int s = pre[lane] + pre[lane + 32] + pre[lane + 64] + pre[lane + 96];
#pragma unroll
        for (int off = 16; off > 0; off >>= 1)
            s += __shfl_down_sync(~0u, s, off);
        if (lane == 0) s_off = s;
    }
    __syncthreads();

    if (i < NN) {
        int ex = s_off + warpoff + x - v;   // exclusive padded prefix
        g_rowptr[i] = ex;
        g_cursor[i] = ex;
        float nv = rsqrtf(fmaxf((float)deg, 1.0f));
        g_norm[i]  = nv;
        g_norm2[i] = nv * nv;
    }
}

// ---------------------------------------------------------------------------
// 3) fused heterogeneous kernel: fill blocks + scale16 blocks.
// ---------------------------------------------------------------------------
__global__ __launch_bounds__(256) void fill_scale_kernel(
    const int4* __restrict__ src4,
    const int4* __restrict__ dst4,
    const float4* __restrict__ feat4) {
    int b = blockIdx.x;
    if (b < FILL_B) {
        int t = b * 256 + threadIdx.x;       // 8 edges per thread
        if (t < NE / 8) {
            int h = t * 2;
            int4 s0 = __ldg(src4 + h), s1 = __ldg(src4 + h + 1);
            int4 d0 = __ldg(dst4 + h), d1 = __ldg(dst4 + h + 1);
            int c0 = atomicAdd(&g_cursor[d0.x], 1);
            int c1 = atomicAdd(&g_cursor[d0.y], 1);
            int c2 = atomicAdd(&g_cursor[d0.z], 1);
            int c3 = atomicAdd(&g_cursor[d0.w], 1);
            int c4 = atomicAdd(&g_cursor[d1.x], 1);
            int c5 = atomicAdd(&g_cursor[d1.y], 1);
            int c6 = atomicAdd(&g_cursor[d1.z], 1);
            int c7 = atomicAdd(&g_cursor[d1.w], 1);
            g_adj[c0] = s0.x; g_adj[c1] = s0.y;
            g_adj[c2] = s0.z; g_adj[c3] = s0.w;
            g_adj[c4] = s1.x; g_adj[c5] = s1.y;
            g_adj[c6] = s1.z; g_adj[c7] = s1.w;
        }
    } else {
        int t = (b - FILL_B) * 256 + threadIdx.x;   // covers NN*8 exactly
        int i = t >> 3;
        int c = t & 7;
        float nv = g_norm[i];
        float4 f0 = __ldg(feat4 + (i << 4) + c * 2);
        float4 f1 = __ldg(feat4 + (i << 4) + c * 2 + 1);
        uint4 u;
        u.x = h2_to_u32(__floats2half2_rn(nv * f0.x, nv * f0.y));
        u.y = h2_to_u32(__floats2half2_rn(nv * f0.z, nv * f0.w));
        u.z = h2_to_u32(__floats2half2_rn(nv * f1.x, nv * f1.y));
        u.w = h2_to_u32(__floats2half2_rn(nv * f1.z, nv * f1.w));
        g_xs16[t] = u;
    }
}

// ---------------------------------------------------------------------------
// 4) gather passes. 8 threads per node; each thread owns 8 halves (16B).
//    Groups of 4 edges reduce in packed fp16 (3 full-rate HADD2 per slot),
//    converting the PARTIAL once per group -> F2F convert-pipe traffic /4.
//    PASS 0: h0[i] = sum xs16[s]; also y16[i] = half(norm2[i]*h0[i]).
//    PASS 1: h1[i] = C1A * sum y16[s].
// ---------------------------------------------------------------------------
template <int PASS>
__global__ __launch_bounds__(256) void gather_kernel() {
    int t = blockIdx.x * blockDim.x + threadIdx.x;   // grid covers NN*8 exactly
    int i = t >> 3;
    int c = t & 7;

    int j   = g_rowptr[i];       // multiple of 4
    int end = j + g_degi[i];
    const uint4* __restrict__ src = (PASS == 0) ? g_xs16 : g_y16;

    float r0 = 0.f, r1 = 0.f, r2 = 0.f, r3 = 0.f;
    float r4 = 0.f, r5 = 0.f, r6 = 0.f, r7 = 0.f;

    // 4-edge group: fp16 tree partial, then one convert+add.
#define GROUP4(S0, S1, S2, S3)                                               \
    {                                                                        \
        uint4 u0 = __ldg(src + ((S0) << 3) + c);                             \
        uint4 u1 = __ldg(src + ((S1) << 3) + c);                             \
        uint4 u2 = __ldg(src + ((S2) << 3) + c);                             \
        uint4 u3 = __ldg(src + ((S3) << 3) + c);                             \
        __half2 p0 = __hadd2(__hadd2(u32_to_h2(u0.x), u32_to_h2(u1.x)),      \
                             __hadd2(u32_to_h2(u2.x), u32_to_h2(u3.x)));     \
        __half2 p1 = __hadd2(__hadd2(u32_to_h2(u0.y), u32_to_h2(u1.y)),      \
                             __hadd2(u32_to_h2(u2.y), u32_to_h2(u3.y)));     \
        __half2 p2 = __hadd2(__hadd2(u32_to_h2(u0.z), u32_to_h2(u1.z)),      \
                             __hadd2(u32_to_h2(u2.z), u32_to_h2(u3.z)));     \
        __half2 p3 = __hadd2(__hadd2(u32_to_h2(u0.w), u32_to_h2(u1.w)),      \
                             __hadd2(u32_to_h2(u2.w), u32_to_h2(u3.w)));     \
        float2 f0 = __half22float2(p0);                                      \
        float2 f1 = __half22float2(p1);                                      \
        float2 f2 = __half22float2(p2);                                      \
        float2 f3 = __half22float2(p3);                                      \
        r0 += f0.x; r1 += f0.y; r2 += f1.x; r3 += f1.y;                      \
        r4 += f2.x; r5 += f2.y; r6 += f3.x; r7 += f3.y;                      \
    }

    for (; j + 8 <= end; j += 8) {
        int4 p0 = *reinterpret_cast<const int4*>(&g_adj[j]);
        int4 p1 = *reinterpret_cast<const int4*>(&g_adj[j + 4]);
        GROUP4(p0.x, p0.y, p0.z, p0.w);
        GROUP4(p1.x, p1.y, p1.z, p1.w);
    }
    if (j + 4 <= end) {
        int4 p0 = *reinterpret_cast<const int4*>(&g_adj[j]);
        GROUP4(p0.x, p0.y, p0.z, p0.w);
        j += 4;
    }
#undef GROUP4
    for (; j < end; j++) {       // 0..3 tail edges, direct fp32 path
        uint4 u = __ldg(src + (g_adj[j] << 3) + c);
        float2 f0 = u32_to_f2(u.x);
        float2 f1 = u32_to_f2(u.y);
        float2 f2 = u32_to_f2(u.z);
        float2 f3 = u32_to_f2(u.w);
        r0 += f0.x; r1 += f0.y; r2 += f1.x; r3 += f1.y;
        r4 += f2.x; r5 += f2.y; r6 += f3.x; r7 += f3.y;
    }

    if (PASS == 0) {
        g_h0[(i << 4) + c * 2]     = make_float4(r0, r1, r2, r3);
        g_h0[(i << 4) + c * 2 + 1] = make_float4(r4, r5, r6, r7);
        float n2 = g_norm2[i];
        uint4 u;
        u.x = h2_to_u32(__floats2half2_rn(n2 * r0, n2 * r1));
        u.y = h2_to_u32(__floats2half2_rn(n2 * r2, n2 * r3));
        u.z = h2_to_u32(__floats2half2_rn(n2 * r4, n2 * r5));
        u.w = h2_to_u32(__floats2half2_rn(n2 * r6, n2 * r7));
        g_y16[t] = u;
    } else {
        g_h1[(i << 4) + c * 2] =
            make_float4(C1A * r0, C1A * r1, C1A * r2, C1A * r3);
        g_h1[(i << 4) + c * 2 + 1] =
            make_float4(C1A * r4, C1A * r5, C1A * r6, C1A * r7);
    }
}

// ---------------------------------------------------------------------------
// 5) fused epilogue GEMM (proven):
//    t0 = feat;  t1 = c1a*n*h0;  t2 = c2a*n*h1 + c2b*t1 - t0
//    out = t0@W0 + t1@W1 + t2@W2 + bias
// ---------------------------------------------------------------------------
__global__ __launch_bounds__(256) void final_kernel(
    const float4* __restrict__ feat4,
    const float4* __restrict__ W4,
    const float4* __restrict__ bias4,
    float4* __restrict__ out4) {
    __shared__ __align__(16) float Ws[3 * 64 * 64];   // 49152 B
    {
        float4* Ws4 = reinterpret_cast<float4*>(Ws);
        for (int i = threadIdx.x; i < 3 * 64 * 16; i += 256)
            Ws4[i] = __ldg(W4 + i);
    }
    __syncthreads();

    const int cg   = threadIdx.x >> 6;
    const int rg   = threadIdx.x & 63;
    const int base = blockIdx.x * 256;

    int   rows[4];
    bool  valid[4];
    float n[4];
#pragma unroll
    for (int r = 0; r < 4; r++) {
        int row  = base + rg + 64 * r;
        valid[r] = row < NN;
        rows[r]  = valid[r] ? row : 0;
        n[r]     = g_norm[rows[r]];
    }

    ull acc[4][8];
#pragma unroll
    for (int r = 0; r < 4; r++)
#pragma unroll
        for (int cp = 0; cp < 8; cp++) acc[r][cp] = 0ULL;

    const ulonglong2* Wp = reinterpret_cast<const ulonglong2*>(Ws);

    for (int dc = 0; dc < 16; dc++) {
        float4 a0[4], a1[4], a2[4];
#pragma unroll
        for (int r = 0; r < 4; r++) {
            int b = (rows[r] << 4) + dc;
            a0[r] = __ldg(feat4 + b);
            a1[r] = g_h0[b];
            a2[r] = g_h1[b];
        }
#pragma unroll
        for (int s = 0; s < 4; s++) {
            const int d = dc * 4 + s;
            ull tt[3][4];
#pragma unroll
            for (int r = 0; r < 4; r++) {
                float t0  = reinterpret_cast<const float*>(&a0[r])[s];
                float h0v = reinterpret_cast<const float*>(&a1[r])[s];
                float h1v = reinterpret_cast<const float*>(&a2[r])[s];
                float t1 = fmaf(C1A * n[r], h0v, C1B * t0);
                float t2 = fmaf(C2A * n[r], h1v, fmaf(C2B, t1, -t0));
                tt[0][r] = pack2(t0);
                tt[1][r] = pack2(t1);
                tt[2][r] = pack2(t2);
            }
#pragma unroll
            for (int k = 0; k < 3; k++) {
                const ulonglong2* p = Wp + (k * 1024 + d * 16 + cg * 4);
                ull w[8];
#pragma unroll
                for (int j = 0; j < 4; j++) {
                    ulonglong2 v = p[j];       // LDS.128, warp-uniform broadcast
                    w[2 * j]     = v.x;
                    w[2 * j + 1] = v.y;
                }
#pragma unroll
                for (int r = 0; r < 4; r++)
#pragma unroll
                    for (int cp = 0; cp < 8; cp++)
                        fma2(acc[r][cp], tt[k][r], w[cp]);
            }
        }
    }

    float4 b4[4];
#pragma unroll
    for (int j = 0; j < 4; j++) b4[j] = __ldg(bias4 + cg * 4 + j);
#pragma unroll
    for (int r = 0; r < 4; r++) {
        if (!valid[r]) continue;
#pragma unroll
        for (int j = 0; j < 4; j++) {
            float2 lo = unpack2(acc[r][2 * j]);
            float2 hi = unpack2(acc[r][2 * j + 1]);
            float4 o;
            o.x = lo.x + b4[j].x;
            o.y = lo.y + b4[j].y;
            o.z = hi.x + b4[j].z;
            o.w = hi.y + b4[j].w;
            out4[(rows[r] << 4) + cg * 4 + j] = o;
        }
    }
}

// ---------------------------------------------------------------------------
// launch (graph-capturable: only async memsets + kernel launches, one stream)
// ---------------------------------------------------------------------------
extern "C" void kernel_launch(void* const* d_in, const int* in_sizes, int n_in,
                              void* d_out, int out_size) {
    const float* feat = (const float*)d_in[0];
    const float* W    = (const float*)d_in[1];
    const float* bias = (const float*)d_in[2];
    const int*   esrc = (const int*)d_in[3];
    const int*   edst = (const int*)d_in[4];
    float*       out  = (float*)d_out;

    void *p_degi = nullptr, *p_tot = nullptr;
    cudaGetSymbolAddress(&p_degi, g_degi);
    cudaGetSymbolAddress(&p_tot,  g_tot);
    cudaMemsetAsync(p_degi, 0, NN * sizeof(int));
    cudaMemsetAsync(p_tot,  0, 128 * sizeof(int));

    const int T = 256;

    deg_kernel<<<(NE / 4 + T - 1) / T, T>>>((const int4*)edst);
    scan_kernel<<<NB, 1024>>>();
    fill_scale_kernel<<<FILL_B + SCALE_B, T>>>((const int4*)esrc,
                                               (const int4*)edst,
                                               (const float4*)feat);

    gather_kernel<0><<<NN * 8 / T, T>>>();
    gather_kernel<1><<<NN * 8 / T, T>>>();

    final_kernel<<<(NN + 255) / 256, 256>>>((const float4*)feat,
                                            (const float4*)W,
                                            (const float4*)bias,
                                            (float4*)out);
}